// round 2
// baseline (speedup 1.0000x reference)
#include <cuda_runtime.h>

// Shapes fixed by the dataset.
#define NCLS   19
#define NBINS  15
#define HW     (512 * 1024)          // 2^19
#define NB     4
#define NPIX   (NB * HW)             // 2,097,152
#define NCELLS (NCLS * NBINS)        // 285
#define NBLOCKS 2048
#define NTHREADS 256

// g_hist[c*15+b] accumulates v = 15*(p - [label==c]) over pixels whose p falls
// in bin b.  sce = sum(|g_hist|) / (15 * C * N).
// Invariant: g_hist == 0 and g_count == 0 at kernel entry; the last block
// restores this before exiting (atomicInc wraps g_count back to 0).
__device__ float    g_hist[NCELLS];
__device__ unsigned g_count;

__global__ __launch_bounds__(NTHREADS)
void ece_fused_kernel(const float* __restrict__ logits,
                      const int*   __restrict__ labels,
                      float*       __restrict__ out) {
    __shared__ float  s_hist[NCELLS];
    __shared__ double s_red[NTHREADS];
    __shared__ bool   s_last;

    for (int i = threadIdx.x; i < NCELLS; i += NTHREADS) s_hist[i] = 0.0f;
    __syncthreads();

    // Cumulative register accumulators: A0 = sum over t<=1, A1 = t<=2, A2 = t<=3
    // (t = 15*p; bin boundaries at integer t).  Bin k sum = A_k - A_{k-1}.
    float A0[NCLS], A1[NCLS], A2[NCLS];
#pragma unroll
    for (int c = 0; c < NCLS; c++) { A0[c] = 0.0f; A1[c] = 0.0f; A2[c] = 0.0f; }

    const unsigned stride = NBLOCKS * NTHREADS;
    for (unsigned i = blockIdx.x * NTHREADS + threadIdx.x; i < (unsigned)NPIX; i += stride) {
        const unsigned b  = i >> 19;              // HW = 2^19
        const unsigned hw = i & (HW - 1);
        const float* base = logits + (size_t)b * (NCLS * HW) + hw;

        // Batch the 19 plane loads (coalesced per warp, MLP = 19).
        float x[NCLS];
#pragma unroll
        for (int c = 0; c < NCLS; c++) x[c] = __ldg(base + c * HW);
        const int lab = __ldg(labels + i);

        // Softmax without max-subtraction: logits ~ N(0,1), |x| < ~6,
        // exp range [2e-3, 4e2] is safe in fp32.
        float S = 0.0f;
#pragma unroll
        for (int c = 0; c < NCLS; c++) { x[c] = __expf(x[c]); S += x[c]; }
        const float inv15 = __fdividef(15.0f, S);

#pragma unroll
        for (int c = 0; c < NCLS; c++) {
            const float t = x[c] * inv15;                    // 15 * p  (> 0 always)
            const float v = (c == lab) ? (t - 15.0f) : t;    // 15*(p - eq)
            if (t <= 1.0f) A0[c] += v;                       // cumulative predicated adds
            if (t <= 2.0f) A1[c] += v;
            if (t <= 3.0f) A2[c] += v;
            if (t > 3.0f) {                                  // rare: p > 0.2
                const int bin = min(__float2int_ru(t) - 1, NBINS - 1);
                atomicAdd(&s_hist[c * NBINS + bin], v);
            }
        }
    }

    // Warp-reduce the register accumulators, lane 0 flushes to shared.
    const int lane = threadIdx.x & 31;
#pragma unroll
    for (int c = 0; c < NCLS; c++) {
        float a0 = A0[c], a1 = A1[c], a2 = A2[c];
#pragma unroll
        for (int s = 16; s > 0; s >>= 1) {
            a0 += __shfl_xor_sync(0xffffffffu, a0, s);
            a1 += __shfl_xor_sync(0xffffffffu, a1, s);
            a2 += __shfl_xor_sync(0xffffffffu, a2, s);
        }
        if (lane == 0) {
            atomicAdd(&s_hist[c * NBINS + 0], a0);
            atomicAdd(&s_hist[c * NBINS + 1], a1 - a0);
            atomicAdd(&s_hist[c * NBINS + 2], a2 - a1);
        }
    }
    __syncthreads();

    // Block flush -> global.
    for (int i = threadIdx.x; i < NCELLS; i += NTHREADS) {
        const float v = s_hist[i];
        if (v != 0.0f) atomicAdd(&g_hist[i], v);
    }

    // Completion protocol (threadFenceReduction pattern).
    __threadfence();
    __syncthreads();
    if (threadIdx.x == 0) {
        const unsigned r = atomicInc(&g_count, NBLOCKS - 1);  // wraps back to 0
        s_last = (r == NBLOCKS - 1);
    }
    __syncthreads();

    if (s_last) {
        __threadfence();   // all other blocks' atomics are visible (gpu-scope acquire)
        double local = 0.0;
        for (int i = threadIdx.x; i < NCELLS; i += NTHREADS) {
            local += fabs((double)g_hist[i]);
            g_hist[i] = 0.0f;                  // restore invariant for next launch
        }
        s_red[threadIdx.x] = local;
        __syncthreads();
        for (int s = NTHREADS / 2; s > 0; s >>= 1) {
            if (threadIdx.x < s) s_red[threadIdx.x] += s_red[threadIdx.x + s];
            __syncthreads();
        }
        if (threadIdx.x == 0) {
            // sce = sum(|diff|)/(C*N), diff = cell/15
            out[0] = (float)(s_red[0] / (15.0 * (double)NCLS * (double)NPIX));
        }
    }
}

extern "C" void kernel_launch(void* const* d_in, const int* in_sizes, int n_in,
                              void* d_out, int out_size) {
    const float* logits;
    const int*   labels;
    if (in_sizes[0] == NPIX) {               // defensive order detection by size
        labels = (const int*)d_in[0];
        logits = (const float*)d_in[1];
    } else {
        logits = (const float*)d_in[0];
        labels = (const int*)d_in[1];
    }
    float* out = (float*)d_out;

    ece_fused_kernel<<<NBLOCKS, NTHREADS>>>(logits, labels, out);
}

// round 3
// speedup vs baseline: 1.4972x; 1.4972x over previous
#include <cuda_runtime.h>

#define NCLS    19
#define NBINS   15
#define HW      (512 * 1024)           // 2^19
#define NB      4
#define NPIX    (NB * HW)              // 2,097,152
#define NQUAD   (NPIX / 4)             // 524,288
#define NCELLS  (NCLS * NBINS)         // 285
#define NLVL    7                      // register (cumulative) bins: t<=1..7
#define P2_GRIDX 64                    // pass-2 blocks per class
#define P2_BLOCKS (NCLS * P2_GRIDX)    // 1216
#define NT      256

// Scratch: inv15[q] = 15 / sum_c exp(logit[c]) for pixel-quad q (float4).
__device__ float4   g_inv15[NQUAD];
// g_hist[c*15+b] = sum of 15*(p - [label==c]) over pixels with bin(p_c)=b.
// Invariant: zero at entry; last pass-2 block restores it.
__device__ float    g_hist[NCELLS];
__device__ unsigned g_count;

// ---------------- Pass 1: softmax denominators ----------------
__global__ __launch_bounds__(NT)
void ece_pass1(const float* __restrict__ logits) {
    const unsigned q = blockIdx.x * NT + threadIdx.x;    // one quad per thread
    const unsigned i  = q << 2;
    const unsigned b  = i >> 19;
    const unsigned hw = i & (HW - 1);
    const float* base = logits + (size_t)b * (NCLS * HW) + hw;

    float4 S = make_float4(0.f, 0.f, 0.f, 0.f);
#pragma unroll
    for (int c = 0; c < NCLS; c++) {
        const float4 x = __ldg((const float4*)(base + c * HW));
        S.x += __expf(x.x); S.y += __expf(x.y);
        S.z += __expf(x.z); S.w += __expf(x.w);
    }
    g_inv15[q] = make_float4(__fdividef(15.f, S.x), __fdividef(15.f, S.y),
                             __fdividef(15.f, S.z), __fdividef(15.f, S.w));
}

// ---------------- Pass 2: per-class binning + finalize ----------------
__global__ __launch_bounds__(NT)
void ece_pass2(const float* __restrict__ logits,
               const int*   __restrict__ labels,
               float*       __restrict__ out) {
    const int c = blockIdx.y;
    __shared__ float  s_rare[NBINS];     // only bins 7..14 are ever touched
    __shared__ float  s_acc[NLVL];
    __shared__ double s_red[NT];
    __shared__ bool   s_last;
    if (threadIdx.x < NBINS) s_rare[threadIdx.x] = 0.f;
    if (threadIdx.x < NLVL)  s_acc[threadIdx.x]  = 0.f;
    __syncthreads();

    // Cumulative accumulators: a[k] = sum of v over class-pixels with t <= k+1.
    float a0=0.f,a1=0.f,a2=0.f,a3=0.f,a4=0.f,a5=0.f,a6=0.f;

    const float* cls = logits + (size_t)c * HW;          // + b*19*HW per quad
    for (unsigned q = blockIdx.x * NT + threadIdx.x; q < NQUAD; q += P2_GRIDX * NT) {
        const unsigned i  = q << 2;
        const unsigned b  = i >> 19;
        const unsigned hw = i & (HW - 1);
        const float4 x  = __ldg((const float4*)(cls + (size_t)b * (NCLS * HW) + hw));
        const float4 w  = __ldg(&g_inv15[q]);            // 15/S (DRAM, streamed)
        const int4   lb = __ldg((const int4*)(labels + i)); // L2-resident re-read

#pragma unroll
        for (int j = 0; j < 4; j++) {
            const float xx = (j==0)?x.x:(j==1)?x.y:(j==2)?x.z:x.w;
            const float ww = (j==0)?w.x:(j==1)?w.y:(j==2)?w.z:w.w;
            const int   ll = (j==0)?lb.x:(j==1)?lb.y:(j==2)?lb.z:lb.w;
            const float t  = __expf(xx) * ww;            // 15*p, > 0 always
            const float v  = (ll == c) ? (t - 15.f) : t; // 15*(p - eq)
            if (t <= 1.f) a0 += v;
            if (t <= 2.f) a1 += v;
            if (t <= 3.f) a2 += v;
            if (t <= 4.f) a3 += v;
            if (t <= 5.f) a4 += v;
            if (t <= 6.f) a5 += v;
            if (t <= 7.f) a6 += v;
            if (t > 7.f) {                               // p > 0.467: ~0.4%/class-pixel
                const int bin = min(__float2int_ru(t) - 1, NBINS - 1);
                atomicAdd(&s_rare[bin], v);
            }
        }
    }

    // Warp-reduce the 7 scalars; lane 0 -> shared.
    const int lane = threadIdx.x & 31;
#pragma unroll
    for (int s = 16; s > 0; s >>= 1) {
        a0 += __shfl_xor_sync(~0u, a0, s);
        a1 += __shfl_xor_sync(~0u, a1, s);
        a2 += __shfl_xor_sync(~0u, a2, s);
        a3 += __shfl_xor_sync(~0u, a3, s);
        a4 += __shfl_xor_sync(~0u, a4, s);
        a5 += __shfl_xor_sync(~0u, a5, s);
        a6 += __shfl_xor_sync(~0u, a6, s);
    }
    if (lane == 0) {
        atomicAdd(&s_acc[0], a0); atomicAdd(&s_acc[1], a1);
        atomicAdd(&s_acc[2], a2); atomicAdd(&s_acc[3], a3);
        atomicAdd(&s_acc[4], a4); atomicAdd(&s_acc[5], a5);
        atomicAdd(&s_acc[6], a6);
    }
    __syncthreads();

    // Flush this block's contribution to g_hist (bins 0..6 = adjacent diffs).
    if (threadIdx.x < NLVL) {
        const float prev = (threadIdx.x == 0) ? 0.f : s_acc[threadIdx.x - 1];
        const float d = s_acc[threadIdx.x] - prev;
        if (d != 0.f) atomicAdd(&g_hist[c * NBINS + threadIdx.x], d);
    } else if (threadIdx.x < NBINS) {
        const float d = s_rare[threadIdx.x];
        if (d != 0.f) atomicAdd(&g_hist[c * NBINS + threadIdx.x], d);
    }

    // Completion protocol.
    __threadfence();
    __syncthreads();
    if (threadIdx.x == 0) {
        const unsigned r = atomicInc(&g_count, P2_BLOCKS - 1);   // wraps to 0
        s_last = (r == P2_BLOCKS - 1);
    }
    __syncthreads();

    if (s_last) {
        __threadfence();
        double local = 0.0;
        for (int i = threadIdx.x; i < NCELLS; i += NT) {
            local += fabs((double)g_hist[i]);
            g_hist[i] = 0.f;                 // restore invariant for next replay
        }
        s_red[threadIdx.x] = local;
        __syncthreads();
        for (int s = NT / 2; s > 0; s >>= 1) {
            if (threadIdx.x < s) s_red[threadIdx.x] += s_red[threadIdx.x + s];
            __syncthreads();
        }
        if (threadIdx.x == 0)
            out[0] = (float)(s_red[0] / (15.0 * (double)NCLS * (double)NPIX));
    }
}

extern "C" void kernel_launch(void* const* d_in, const int* in_sizes, int n_in,
                              void* d_out, int out_size) {
    const float* logits;
    const int*   labels;
    if (in_sizes[0] == NPIX) {           // defensive order detection by size
        labels = (const int*)d_in[0];
        logits = (const float*)d_in[1];
    } else {
        logits = (const float*)d_in[0];
        labels = (const int*)d_in[1];
    }
    float* out = (float*)d_out;

    ece_pass1<<<NQUAD / NT, NT>>>(logits);
    dim3 g2(P2_GRIDX, NCLS);
    ece_pass2<<<g2, NT>>>(logits, labels, out);
}